// round 1
// baseline (speedup 1.0000x reference)
#include <cuda_runtime.h>
#include <math.h>
#include <stdint.h>

// Problem constants
#define TT 256
#define BB 128
#define FF 1024
#define UU 512
#define G4 (4*UU)      // 2048
#define CODES 1024
#define MROWS (TT*BB)  // 32768

// Scratch (device globals: allocation-free per harness rules)
__device__ float g_xz[(size_t)MROWS * G4];      // [T*B, 4U]  256 MB
__device__ float g_hseq[(size_t)MROWS * UU];    // [T*B, U]    64 MB
__device__ float g_z[(size_t)BB * G4];          // [B, 4U] step scratch
__device__ float g_c[(size_t)BB * UU];          // cell state
__device__ float g_h0[(size_t)BB * UU];         // zero-initialized, never written

// ---------------------------------------------------------------------------
// Generic tiled fp32 SGEMM: C = op( A(*maskA) @ B + Cin + bias )
// A: [M,K] row-major, B: [K,N] row-major, C: [M,N].
// All dims divisible by tile sizes (asserted by construction of call sites).
// ---------------------------------------------------------------------------
template<int BM,int BN,int BK,int TM,int TN,bool MASK_A,bool ADD_BIAS,bool RELU,bool LOAD_C>
__global__ void sgemm_kernel(int M, int N, int K,
                             const float* __restrict__ A,
                             const float* __restrict__ Bm,
                             float* __restrict__ C,
                             const float* __restrict__ bias,
                             const float* __restrict__ maskA,
                             const float* __restrict__ Cin)
{
    constexpr int THREADS = (BM/TM)*(BN/TN);
    __shared__ float As[BK][BM];
    __shared__ float Bs[BK][BN];

    const int tid  = threadIdx.x;
    const int tcol = tid % (BN/TN);
    const int trow = tid / (BN/TN);
    const int brow = blockIdx.y * BM;
    const int bcol = blockIdx.x * BN;

    float acc[TM][TN];
#pragma unroll
    for (int i = 0; i < TM; i++)
#pragma unroll
        for (int j = 0; j < TN; j++) acc[i][j] = 0.f;

    for (int k0 = 0; k0 < K; k0 += BK) {
        // Load A tile (transposed into smem), vectorized float4
#pragma unroll
        for (int i = tid; i < BM*BK/4; i += THREADS) {
            int r = i / (BK/4);
            int c = (i % (BK/4)) * 4;
            float4 v = *(const float4*)(A + (size_t)(brow + r) * K + k0 + c);
            if (MASK_A) {
                float m = maskA[brow + r];
                v.x *= m; v.y *= m; v.z *= m; v.w *= m;
            }
            As[c+0][r] = v.x; As[c+1][r] = v.y; As[c+2][r] = v.z; As[c+3][r] = v.w;
        }
        // Load B tile
#pragma unroll
        for (int i = tid; i < BK*BN/4; i += THREADS) {
            int r = i / (BN/4);
            int c = (i % (BN/4)) * 4;
            *(float4*)&Bs[r][c] = *(const float4*)(Bm + (size_t)(k0 + r) * N + bcol + c);
        }
        __syncthreads();

#pragma unroll
        for (int kk = 0; kk < BK; kk++) {
            float ra[TM], rb[TN];
#pragma unroll
            for (int i = 0; i < TM; i++) ra[i] = As[kk][trow*TM + i];
#pragma unroll
            for (int j = 0; j < TN; j++) rb[j] = Bs[kk][tcol*TN + j];
#pragma unroll
            for (int i = 0; i < TM; i++)
#pragma unroll
                for (int j = 0; j < TN; j++)
                    acc[i][j] = fmaf(ra[i], rb[j], acc[i][j]);
        }
        __syncthreads();
    }

    // Epilogue
#pragma unroll
    for (int i = 0; i < TM; i++) {
        int row = brow + trow*TM + i;
#pragma unroll
        for (int j = 0; j < TN; j += 4) {
            int col = bcol + tcol*TN + j;
            float4 v = make_float4(acc[i][j], acc[i][j+1], acc[i][j+2], acc[i][j+3]);
            if (LOAD_C) {
                float4 ci = *(const float4*)(Cin + (size_t)row * N + col);
                v.x += ci.x; v.y += ci.y; v.z += ci.z; v.w += ci.w;
            }
            if (ADD_BIAS) {
                float4 bi = *(const float4*)(bias + col);
                v.x += bi.x; v.y += bi.y; v.z += bi.z; v.w += bi.w;
            }
            if (RELU) {
                v.x = fmaxf(v.x, 0.f); v.y = fmaxf(v.y, 0.f);
                v.z = fmaxf(v.z, 0.f); v.w = fmaxf(v.w, 0.f);
            }
            *(float4*)(C + (size_t)row * N + col) = v;
        }
    }
}

// ---------------------------------------------------------------------------
// LSTM gate update for one timestep.
// z: [B, 4U] with Keras gate order i,f,g,o; c: [B,U] in/out; h_out: [B,U]
// ---------------------------------------------------------------------------
__global__ void gate_kernel(const float* __restrict__ z,
                            float* __restrict__ c,
                            float* __restrict__ h_out)
{
    int idx = blockIdx.x * blockDim.x + threadIdx.x;
    if (idx >= BB * UU) return;
    int b = idx / UU;
    int u = idx - b * UU;
    const float* zr = z + (size_t)b * G4;
    float zi = zr[u];
    float zf = zr[UU + u];
    float zg = zr[2*UU + u];
    float zo = zr[3*UU + u];
    float ig = 1.f / (1.f + expf(-zi));
    float fg = 1.f / (1.f + expf(-zf));
    float gg = tanhf(zg);
    float og = 1.f / (1.f + expf(-zo));
    float cn = fg * c[idx] + ig * gg;
    c[idx] = cn;
    h_out[idx] = og * tanhf(cn);
}

__global__ void zero_kernel(float* __restrict__ p, int n)
{
    int idx = blockIdx.x * blockDim.x + threadIdx.x;
    if (idx < n) p[idx] = 0.f;
}

// ---------------------------------------------------------------------------
// In-place row softmax over CODES=1024 columns. One block per row, 256 thr.
// ---------------------------------------------------------------------------
__global__ void softmax_kernel(float* __restrict__ out)
{
    const int row = blockIdx.x;
    float* p = out + (size_t)row * CODES;
    const int t = threadIdx.x;

    float v[4];
#pragma unroll
    for (int i = 0; i < 4; i++) v[i] = p[t + 256*i];

    __shared__ float red_max[8];
    __shared__ float red_sum[8];

    float m = fmaxf(fmaxf(v[0], v[1]), fmaxf(v[2], v[3]));
#pragma unroll
    for (int o = 16; o > 0; o >>= 1) m = fmaxf(m, __shfl_xor_sync(0xffffffffu, m, o));
    if ((t & 31) == 0) red_max[t >> 5] = m;
    __syncthreads();
    m = red_max[0];
#pragma unroll
    for (int i = 1; i < 8; i++) m = fmaxf(m, red_max[i]);

    float s = 0.f;
#pragma unroll
    for (int i = 0; i < 4; i++) { v[i] = expf(v[i] - m); s += v[i]; }
#pragma unroll
    for (int o = 16; o > 0; o >>= 1) s += __shfl_xor_sync(0xffffffffu, s, o);
    if ((t & 31) == 0) red_sum[t >> 5] = s;
    __syncthreads();
    s = 0.f;
#pragma unroll
    for (int i = 0; i < 8; i++) s += red_sum[i];

    float inv = 1.f / s;
#pragma unroll
    for (int i = 0; i < 4; i++) p[t + 256*i] = v[i] * inv;
}

// ---------------------------------------------------------------------------
// Launch: inputs in metadata order:
//   0: x [T,B,F]  1: mask [T,B]  2: W_in [F,4U]  3: W_rec [U,4U]
//   4: b_lstm [4U]  5: W_dense [U,CODES]  6: b_dense [CODES]
// out: [T,B,CODES] float32
// ---------------------------------------------------------------------------
extern "C" void kernel_launch(void* const* d_in, const int* in_sizes, int n_in,
                              void* d_out, int out_size)
{
    (void)in_sizes; (void)n_in; (void)out_size;
    const float* x       = (const float*)d_in[0];
    const float* mask    = (const float*)d_in[1];
    const float* W_in    = (const float*)d_in[2];
    const float* W_rec   = (const float*)d_in[3];
    const float* b_lstm  = (const float*)d_in[4];
    const float* W_dense = (const float*)d_in[5];
    const float* b_dense = (const float*)d_in[6];
    float* out = (float*)d_out;

    float *xz, *hseq, *z, *c, *h0;
    cudaGetSymbolAddress((void**)&xz,   g_xz);
    cudaGetSymbolAddress((void**)&hseq, g_hseq);
    cudaGetSymbolAddress((void**)&z,    g_z);
    cudaGetSymbolAddress((void**)&c,    g_c);
    cudaGetSymbolAddress((void**)&h0,   g_h0);

    // 1. zero the cell state (graph replays must be deterministic)
    zero_kernel<<<(BB*UU + 255)/256, 256>>>(c, BB*UU);

    // 2. xz = x @ W_in + b_lstm   [32768 x 2048], K=1024
    {
        dim3 grid(G4/128, MROWS/128);
        sgemm_kernel<128,128,16,8,8,false,true,false,false>
            <<<grid, 256>>>(MROWS, G4, FF, x, W_in, xz, b_lstm, nullptr, nullptr);
    }

    // 3. recurrence: 256 sequential steps
    for (int t = 0; t < TT; t++) {
        const float* h_prev = (t == 0) ? h0 : (hseq + (size_t)(t-1)*BB*UU);
        const float* xz_t = xz + (size_t)t * BB * G4;
        dim3 grid(G4/64, BB/64);
        sgemm_kernel<64,64,16,4,4,false,false,false,true>
            <<<grid, 256>>>(BB, G4, UU, h_prev, W_rec, z, nullptr, nullptr, xz_t);
        gate_kernel<<<(BB*UU + 255)/256, 256>>>(z, c, hseq + (size_t)t*BB*UU);
    }

    // 4. logits = relu((h_seq * mask) @ W_dense + b_dense)   [32768 x 1024], K=512
    {
        dim3 grid(CODES/128, MROWS/128);
        sgemm_kernel<128,128,16,8,8,true,true,true,false>
            <<<grid, 256>>>(MROWS, CODES, UU, hseq, W_dense, out, b_dense, mask, nullptr);
    }

    // 5. softmax in-place over last dim
    softmax_kernel<<<MROWS, 256>>>(out);
}

// round 3
// speedup vs baseline: 1.2827x; 1.2827x over previous
#include <cuda_runtime.h>
#include <math.h>
#include <stdint.h>

// Problem constants
#define TT 256
#define BB 128
#define FF 1024
#define UU 512
#define G4 (4*UU)      // 2048
#define CODES 1024
#define MROWS (TT*BB)  // 32768

// Scratch (device globals: allocation-free per harness rules)
__device__ float g_xz[(size_t)MROWS * G4];      // [T*B, 4U]  256 MB
__device__ float g_hseq[(size_t)MROWS * UU];    // [T*B, U]    64 MB
__device__ float g_h0[(size_t)BB * UU];         // zero-initialized, never written

// Grid-barrier state (monotone gen; count returns to 0 -> graph-replay safe)
__device__ unsigned g_bar_count;
__device__ unsigned g_bar_gen;

// ---------------------------------------------------------------------------
// Generic tiled fp32 SGEMM: C = op( A(*maskA) @ B + Cin + bias )
// ---------------------------------------------------------------------------
template<int BM,int BN,int BK,int TM,int TN,bool MASK_A,bool ADD_BIAS,bool RELU,bool LOAD_C>
__global__ void sgemm_kernel(int M, int N, int K,
                             const float* __restrict__ A,
                             const float* __restrict__ Bm,
                             float* __restrict__ C,
                             const float* __restrict__ bias,
                             const float* __restrict__ maskA,
                             const float* __restrict__ Cin)
{
    constexpr int THREADS = (BM/TM)*(BN/TN);
    __shared__ float As[BK][BM];
    __shared__ float Bs[BK][BN];

    const int tid  = threadIdx.x;
    const int tcol = tid % (BN/TN);
    const int trow = tid / (BN/TN);
    const int brow = blockIdx.y * BM;
    const int bcol = blockIdx.x * BN;

    float acc[TM][TN];
#pragma unroll
    for (int i = 0; i < TM; i++)
#pragma unroll
        for (int j = 0; j < TN; j++) acc[i][j] = 0.f;

    for (int k0 = 0; k0 < K; k0 += BK) {
#pragma unroll
        for (int i = tid; i < BM*BK/4; i += THREADS) {
            int r = i / (BK/4);
            int c = (i % (BK/4)) * 4;
            float4 v = *(const float4*)(A + (size_t)(brow + r) * K + k0 + c);
            if (MASK_A) {
                float m = maskA[brow + r];
                v.x *= m; v.y *= m; v.z *= m; v.w *= m;
            }
            As[c+0][r] = v.x; As[c+1][r] = v.y; As[c+2][r] = v.z; As[c+3][r] = v.w;
        }
#pragma unroll
        for (int i = tid; i < BK*BN/4; i += THREADS) {
            int r = i / (BN/4);
            int c = (i % (BN/4)) * 4;
            *(float4*)&Bs[r][c] = *(const float4*)(Bm + (size_t)(k0 + r) * N + bcol + c);
        }
        __syncthreads();

#pragma unroll
        for (int kk = 0; kk < BK; kk++) {
            float ra[TM], rb[TN];
#pragma unroll
            for (int i = 0; i < TM; i++) ra[i] = As[kk][trow*TM + i];
#pragma unroll
            for (int j = 0; j < TN; j++) rb[j] = Bs[kk][tcol*TN + j];
#pragma unroll
            for (int i = 0; i < TM; i++)
#pragma unroll
                for (int j = 0; j < TN; j++)
                    acc[i][j] = fmaf(ra[i], rb[j], acc[i][j]);
        }
        __syncthreads();
    }

#pragma unroll
    for (int i = 0; i < TM; i++) {
        int row = brow + trow*TM + i;
#pragma unroll
        for (int j = 0; j < TN; j += 4) {
            int col = bcol + tcol*TN + j;
            float4 v = make_float4(acc[i][j], acc[i][j+1], acc[i][j+2], acc[i][j+3]);
            if (LOAD_C) {
                float4 ci = *(const float4*)(Cin + (size_t)row * N + col);
                v.x += ci.x; v.y += ci.y; v.z += ci.z; v.w += ci.w;
            }
            if (ADD_BIAS) {
                float4 bi = *(const float4*)(bias + col);
                v.x += bi.x; v.y += bi.y; v.z += bi.z; v.w += bi.w;
            }
            if (RELU) {
                v.x = fmaxf(v.x, 0.f); v.y = fmaxf(v.y, 0.f);
                v.z = fmaxf(v.z, 0.f); v.w = fmaxf(v.w, 0.f);
            }
            *(float4*)(C + (size_t)row * N + col) = v;
        }
    }
}

// ---------------------------------------------------------------------------
// Persistent LSTM recurrence: all 256 timesteps in ONE kernel.
// Grid: 128 CTAs (1 per SM via 132KB dynamic smem -> all wave-1 resident),
// 256 threads each. CTA b owns units u0=b*4..u0+3 (16 z-cols = 4 gates x 4 u).
// W_rec slice (512x16) resident in smem for the whole kernel.
// Cell state c lives in registers for the whole sequence.
// Gate math fused; one software grid barrier per step.
// ---------------------------------------------------------------------------
#define LSTM_NBLK 128
#define LSTM_THR  256
#define LSTM_BK   64
#define AS_STRIDE 130          // even (8B-align for float2), bank-friendly
#define WS_FLOATS (UU*16)      // 512*16
#define LSTM_SMEM_BYTES (132*1024)   // forces exactly 1 CTA/SM

__device__ __forceinline__ void grid_barrier()
{
    __threadfence();
    __syncthreads();
    if (threadIdx.x == 0) {
        unsigned gen = *(volatile unsigned*)&g_bar_gen;
        unsigned t = atomicAdd(&g_bar_count, 1);
        if (t == LSTM_NBLK - 1) {
            g_bar_count = 0;
            __threadfence();
            atomicAdd(&g_bar_gen, 1);
        } else {
            while (*(volatile unsigned*)&g_bar_gen == gen) { __nanosleep(40); }
        }
        __threadfence();
    }
    __syncthreads();
}

__global__ void __launch_bounds__(LSTM_THR)
lstm_persistent_kernel(const float* __restrict__ xz,
                       const float* __restrict__ W_rec,
                       float* __restrict__ hseq,
                       const float* __restrict__ h0)
{
    extern __shared__ float smem[];
    float* Ws = smem;                 // [512][16]: Ws[k][ul*4+gate]
    float* As = smem + WS_FLOATS;     // [2][BK][AS_STRIDE] transposed h tile

    const int tid  = threadIdx.x;
    const int tcol = tid & 3;         // u_local 0..3
    const int trow = tid >> 2;        // 0..63
    const int r0   = trow * 2;        // two batch rows per thread
    const int u0   = blockIdx.x * 4;
    const int u    = u0 + tcol;

    // Load W_rec slice once: Ws[k][ul*4+g] = W_rec[k][g*512 + u0 + ul]
    for (int i = tid; i < UU * 4; i += LSTM_THR) {
        int k = i >> 2;
        int g = i & 3;
        float4 v = *(const float4*)(W_rec + (size_t)k * G4 + g * UU + u0);
        Ws[k*16 + 0*4 + g] = v.x;
        Ws[k*16 + 1*4 + g] = v.y;
        Ws[k*16 + 2*4 + g] = v.z;
        Ws[k*16 + 3*4 + g] = v.w;
    }
    __syncthreads();

    float c0 = 0.f, c1 = 0.f;   // cell state, resident in registers

    for (int t = 0; t < TT; t++) {
        const float* hp = (t == 0) ? h0 : (hseq + (size_t)(t-1) * BB * UU);

        // ---- load chunk 0 into buffer 0 (float4 LDG -> transposed STS) ----
#pragma unroll
        for (int j = 0; j < 8; j++) {
            int f  = tid + 256*j;
            int r  = f >> 4;
            int c4 = f & 15;
            float4 v = *(const float4*)(hp + (size_t)r * UU + c4*4);
            float* Ab = As;  // buffer 0
            Ab[(c4*4+0)*AS_STRIDE + r] = v.x;
            Ab[(c4*4+1)*AS_STRIDE + r] = v.y;
            Ab[(c4*4+2)*AS_STRIDE + r] = v.z;
            Ab[(c4*4+3)*AS_STRIDE + r] = v.w;
        }
        __syncthreads();

        float acc0[4] = {0.f,0.f,0.f,0.f};
        float acc1[4] = {0.f,0.f,0.f,0.f};

#pragma unroll 1
        for (int ch = 0; ch < UU/LSTM_BK; ch++) {
            // prefetch next chunk into registers (overlaps with compute)
            float4 pf[8];
            if (ch < UU/LSTM_BK - 1) {
                int k0n = (ch+1) * LSTM_BK;
#pragma unroll
                for (int j = 0; j < 8; j++) {
                    int f  = tid + 256*j;
                    int r  = f >> 4;
                    int c4 = f & 15;
                    pf[j] = *(const float4*)(hp + (size_t)r * UU + k0n + c4*4);
                }
            }

            const float* Ab = As + (ch & 1) * (LSTM_BK * AS_STRIDE);
            const int k0 = ch * LSTM_BK;
#pragma unroll 16
            for (int kk = 0; kk < LSTM_BK; kk++) {
                float2 a = *(const float2*)(Ab + kk*AS_STRIDE + r0);
                float4 w = *(const float4*)(Ws + (size_t)(k0+kk)*16 + tcol*4);
                acc0[0] = fmaf(a.x, w.x, acc0[0]);
                acc0[1] = fmaf(a.x, w.y, acc0[1]);
                acc0[2] = fmaf(a.x, w.z, acc0[2]);
                acc0[3] = fmaf(a.x, w.w, acc0[3]);
                acc1[0] = fmaf(a.y, w.x, acc1[0]);
                acc1[1] = fmaf(a.y, w.y, acc1[1]);
                acc1[2] = fmaf(a.y, w.z, acc1[2]);
                acc1[3] = fmaf(a.y, w.w, acc1[3]);
            }

            if (ch < UU/LSTM_BK - 1) {
                float* Anb = As + ((ch+1) & 1) * (LSTM_BK * AS_STRIDE);
#pragma unroll
                for (int j = 0; j < 8; j++) {
                    int f  = tid + 256*j;
                    int r  = f >> 4;
                    int c4 = f & 15;
                    Anb[(c4*4+0)*AS_STRIDE + r] = pf[j].x;
                    Anb[(c4*4+1)*AS_STRIDE + r] = pf[j].y;
                    Anb[(c4*4+2)*AS_STRIDE + r] = pf[j].z;
                    Anb[(c4*4+3)*AS_STRIDE + r] = pf[j].w;
                }
            }
            __syncthreads();
        }

        // ---- fused gate epilogue (z = acc + xz_t; Keras order i,f,g,o) ----
        const float* xzr = xz + ((size_t)t * BB) * G4;
        {
            const float* x0 = xzr + (size_t)r0 * G4;
            float zi = acc0[0] + x0[0*UU + u];
            float zf = acc0[1] + x0[1*UU + u];
            float zg = acc0[2] + x0[2*UU + u];
            float zo = acc0[3] + x0[3*UU + u];
            float ig = 1.f / (1.f + expf(-zi));
            float fg = 1.f / (1.f + expf(-zf));
            float gg = tanhf(zg);
            float og = 1.f / (1.f + expf(-zo));
            c0 = fg * c0 + ig * gg;
            hseq[((size_t)t * BB + r0) * UU + u] = og * tanhf(c0);
        }
        {
            const float* x1 = xzr + (size_t)(r0+1) * G4;
            float zi = acc1[0] + x1[0*UU + u];
            float zf = acc1[1] + x1[1*UU + u];
            float zg = acc1[2] + x1[2*UU + u];
            float zo = acc1[3] + x1[3*UU + u];
            float ig = 1.f / (1.f + expf(-zi));
            float fg = 1.f / (1.f + expf(-zf));
            float gg = tanhf(zg);
            float og = 1.f / (1.f + expf(-zo));
            c1 = fg * c1 + ig * gg;
            hseq[((size_t)t * BB + r0+1) * UU + u] = og * tanhf(c1);
        }

        grid_barrier();
    }
}

// ---------------------------------------------------------------------------
// In-place row softmax over CODES=1024 columns. One block per row, 256 thr.
// ---------------------------------------------------------------------------
__global__ void softmax_kernel(float* __restrict__ out)
{
    const int row = blockIdx.x;
    float* p = out + (size_t)row * CODES;
    const int t = threadIdx.x;

    float v[4];
#pragma unroll
    for (int i = 0; i < 4; i++) v[i] = p[t + 256*i];

    __shared__ float red_max[8];
    __shared__ float red_sum[8];

    float m = fmaxf(fmaxf(v[0], v[1]), fmaxf(v[2], v[3]));
#pragma unroll
    for (int o = 16; o > 0; o >>= 1) m = fmaxf(m, __shfl_xor_sync(0xffffffffu, m, o));
    if ((t & 31) == 0) red_max[t >> 5] = m;
    __syncthreads();
    m = red_max[0];
#pragma unroll
    for (int i = 1; i < 8; i++) m = fmaxf(m, red_max[i]);

    float s = 0.f;
#pragma unroll
    for (int i = 0; i < 4; i++) { v[i] = expf(v[i] - m); s += v[i]; }
#pragma unroll
    for (int o = 16; o > 0; o >>= 1) s += __shfl_xor_sync(0xffffffffu, s, o);
    if ((t & 31) == 0) red_sum[t >> 5] = s;
    __syncthreads();
    s = 0.f;
#pragma unroll
    for (int i = 0; i < 8; i++) s += red_sum[i];

    float inv = 1.f / s;
#pragma unroll
    for (int i = 0; i < 4; i++) p[t + 256*i] = v[i] * inv;
}

// ---------------------------------------------------------------------------
// Launch: inputs in metadata order:
//   0: x [T,B,F]  1: mask [T,B]  2: W_in [F,4U]  3: W_rec [U,4U]
//   4: b_lstm [4U]  5: W_dense [U,CODES]  6: b_dense [CODES]
// out: [T,B,CODES] float32
// ---------------------------------------------------------------------------
extern "C" void kernel_launch(void* const* d_in, const int* in_sizes, int n_in,
                              void* d_out, int out_size)
{
    (void)in_sizes; (void)n_in; (void)out_size;
    const float* x       = (const float*)d_in[0];
    const float* mask    = (const float*)d_in[1];
    const float* W_in    = (const float*)d_in[2];
    const float* W_rec   = (const float*)d_in[3];
    const float* b_lstm  = (const float*)d_in[4];
    const float* W_dense = (const float*)d_in[5];
    const float* b_dense = (const float*)d_in[6];
    float* out = (float*)d_out;

    float *xz, *hseq, *h0;
    cudaGetSymbolAddress((void**)&xz,   g_xz);
    cudaGetSymbolAddress((void**)&hseq, g_hseq);
    cudaGetSymbolAddress((void**)&h0,   g_h0);

    // 1. xz = x @ W_in + b_lstm   [32768 x 2048], K=1024
    {
        dim3 grid(G4/128, MROWS/128);
        sgemm_kernel<128,128,16,8,8,false,true,false,false>
            <<<grid, 256>>>(MROWS, G4, FF, x, W_in, xz, b_lstm, nullptr, nullptr);
    }

    // 2. recurrence: single persistent kernel, all 256 steps
    //    (attribute set unconditionally every call — no static guards)
    cudaFuncSetAttribute(lstm_persistent_kernel,
                         cudaFuncAttributeMaxDynamicSharedMemorySize,
                         LSTM_SMEM_BYTES);
    lstm_persistent_kernel<<<LSTM_NBLK, LSTM_THR, LSTM_SMEM_BYTES>>>(
        xz, W_rec, hseq, h0);

    // 3. logits = relu((h_seq * mask) @ W_dense + b_dense)   [32768 x 1024], K=512
    {
        dim3 grid(CODES/128, MROWS/128);
        sgemm_kernel<128,128,16,8,8,true,true,true,false>
            <<<grid, 256>>>(MROWS, CODES, UU, hseq, W_dense, out, b_dense, mask, nullptr);
    }

    // 4. softmax in-place over last dim
    softmax_kernel<<<MROWS, 256>>>(out);
}